// round 6
// baseline (speedup 1.0000x reference)
#include <cuda_runtime.h>
#include <cuda_fp16.h>
#include <cstdint>

#define NN 4096
#define NB 32
#define PA 3072      /* u32 per fragment panel: 128 rows/cols x 48 k fp16 pairs */
#define SCALE2 (0.28867513459481287f * 1.4426950408889634f)  /* (1/sqrt12)*log2e */

typedef unsigned int u32;

/* ---------------- global scratch ----------------------------------------- */
__device__ __align__(16) u32   g_qA[8*NB*PA];     /* Q as mma-A frags (pass2) */
__device__ __align__(16) u32   g_qB[8*NB*PA];     /* Q as mma-B frags (pass1) */
__device__ __align__(16) u32   g_kA[8*NB*PA];     /* K as mma-A frags (pass1) */
__device__ __align__(16) u32   g_kB[8*NB*PA];     /* K as mma-B frags (pass2) */
__device__ __align__(16) u32   g_vB[8*NB*PA];     /* v/D as mma-B frags (pass2) */
__device__ __align__(16) float g_v [8*48*NN];     /* fp32 v, rows 36..47 zero */

/* ---------------- helpers ------------------------------------------------ */
__device__ __forceinline__ void mma_h(float* d, uint4 a, uint2 b){
    asm("mma.sync.aligned.m16n8k16.row.col.f32.f16.f16.f32 "
        "{%0,%1,%2,%3},{%4,%5,%6,%7},{%8,%9},{%0,%1,%2,%3};"
        : "+f"(d[0]), "+f"(d[1]), "+f"(d[2]), "+f"(d[3])
        : "r"(a.x), "r"(a.y), "r"(a.z), "r"(a.w), "r"(b.x), "r"(b.y));
}
__device__ __forceinline__ u32 pkh(float lo, float hi){
    __half2 h = __floats2half2_rn(lo, hi);
    return *(u32*)&h;
}
__device__ __forceinline__ float ex2f(float x){
    float r; asm("ex2.approx.f32 %0, %1;" : "=f"(r) : "f"(x)); return r;
}
__device__ __forceinline__ u32 smem_u32(const void* p){
    u32 a;
    asm("{ .reg .u64 t; cvta.to.shared.u64 t, %1; cvt.u32.u64 %0, t; }" : "=r"(a) : "l"(p));
    return a;
}
__device__ __forceinline__ void cpa16(u32 d, const void* s){
    asm volatile("cp.async.ca.shared.global [%0], [%1], 16;" :: "r"(d), "l"(s));
}
#define CP_COMMIT() asm volatile("cp.async.commit_group;")
#define CP_WAIT1()  asm volatile("cp.async.wait_group 1;")

/* ================= Kernel A: QKV -> fp16 fragment panels (x4) ============ */
__global__ __launch_bounds__(128)
void qkv_kernel(const float* __restrict__ x,
                const float* __restrict__ wq, const float* __restrict__ bq,
                const float* __restrict__ wk, const float* __restrict__ bk,
                const float* __restrict__ wv, const float* __restrict__ bv)
{
    __shared__ float w_s[3*432];
    __shared__ float b_s[3*36];
    const int t = threadIdx.x;
    const int b = blockIdx.y, nblk = blockIdx.x;
    const int n = nblk*128 + t;

    for (int i = t; i < 432; i += 128){ w_s[i]=wq[i]; w_s[432+i]=wk[i]; w_s[864+i]=wv[i]; }
    if (t < 36){ b_s[t]=bq[t]; b_s[36+t]=bk[t]; b_s[72+t]=bv[t]; }
    __syncthreads();

    float xv[12];
    #pragma unroll
    for (int c = 0; c < 12; ++c) xv[c] = x[(b*12 + c)*NN + n];

    float qv[36], kv[36];
    #pragma unroll 4
    for (int o = 0; o < 36; ++o){
        float q = b_s[o], k = b_s[36+o], v = b_s[72+o];
        #pragma unroll
        for (int c = 0; c < 12; ++c){
            q += w_s[o*12+c]*xv[c];
            k += w_s[432+o*12+c]*xv[c];
            v += w_s[864+o*12+c]*xv[c];
        }
        qv[o] = q*SCALE2;   /* fold softmax scale AND log2e */
        kv[o] = k;
        g_v[((long)(b*48+o))*NN + n] = v;
    }
    #pragma unroll
    for (int o = 36; o < 48; ++o) g_v[((long)(b*48+o))*NN + n] = 0.f;

    const int base = (b*NB + nblk)*PA;
    const int rt = t >> 4, lr = t & 15;     /* A coords: row = t */
    const int ct = t >> 3, gB = t & 7;      /* B coords: col = t */

    #pragma unroll
    for (int p = 0; p < 24; ++p){
        const int kk = p >> 3, cp = p & 7;
        const int c0 = kk*16 + cp*2, c1 = c0 + 1;
        const float q0 = (c0 < 36) ? qv[c0] : 0.f, q1 = (c1 < 36) ? qv[c1] : 0.f;
        const float k0 = (c0 < 36) ? kv[c0] : 0.f, k1 = (c1 < 36) ? kv[c1] : 0.f;
        const u32 qp = pkh(q0, q1), kp = pkh(k0, k1);
        /* A-frags */
        const int regA  = ((cp >> 2) << 1) | (lr >> 3);
        const int laneA = ((lr & 7) << 2) | (cp & 3);
        const int aoff  = base + (rt*3 + kk)*128 + laneA*4 + regA;
        g_qA[aoff] = qp;
        g_kA[aoff] = kp;
        /* B-frags */
        const int regB  = cp >> 2;
        const int laneB = (gB << 2) | (cp & 3);
        const int boff  = base + (ct*3 + kk)*64 + laneB*2 + regB;
        g_qB[boff] = qp;
        g_kB[boff] = kp;
    }
}

/* ====== Pass 1: S = K·Q^T (n rows) -> D[n] -> vp = v/D B-frags =========== */
__global__ __launch_bounds__(256)
void pass1_kernel()
{
    __shared__ u32 qb[2][PA];
    __shared__ float Dsh[128];
    __shared__ float invd[128];

    const int t = threadIdx.x, w = t >> 5, lane = t & 31;
    const int g = lane >> 2, tg = lane & 3;
    const int b = blockIdx.y, nblk = blockIdx.x;

    /* K A-frags: warp w owns n-rows w*16..+15 */
    uint4 a[3];
    {
        const u32* kA = g_kA + (b*NB + nblk)*PA;
        #pragma unroll
        for (int ck = 0; ck < 3; ++ck)
            a[ck] = *(const uint4*)(kA + (w*3 + ck)*128 + lane*4);
    }

    const char* qsrc = (const char*)(g_qB + (long)b*NB*PA);
    { const u32 d = smem_u32(qb[0]); for (int i = t; i < 768; i += 256) cpa16(d + i*16, qsrc + i*16); }
    CP_COMMIT();

    float rs0 = 0.f, rs1 = 0.f;

    for (int mc = 0; mc < NB; ++mc){
        const u32* cur = qb[mc & 1];
        if (mc + 1 < NB){
            const u32 d = smem_u32(qb[(mc + 1) & 1]);
            const char* s = qsrc + (long)(mc + 1)*PA*4;
            for (int i = t; i < 768; i += 256) cpa16(d + i*16, s + i*16);
        }
        CP_COMMIT(); CP_WAIT1();
        __syncthreads();

        #pragma unroll 4
        for (int ctb = 0; ctb < 16; ++ctb){
            float acc[4] = {0.f, 0.f, 0.f, 0.f};
            #pragma unroll
            for (int ck = 0; ck < 3; ++ck){
                const uint2 bq = *(const uint2*)(cur + (ctb*3 + ck)*64 + lane*2);
                mma_h(acc, a[ck], bq);
            }
            rs0 += ex2f(fminf(acc[0],15.f)) + ex2f(fminf(acc[1],15.f));
            rs1 += ex2f(fminf(acc[2],15.f)) + ex2f(fminf(acc[3],15.f));
        }
        __syncthreads();
    }

    /* reduce over m-col lanes (tg) -> D for rows w*16+g / +8+g */
    rs0 += __shfl_xor_sync(0xFFFFFFFFu, rs0, 1);
    rs0 += __shfl_xor_sync(0xFFFFFFFFu, rs0, 2);
    rs1 += __shfl_xor_sync(0xFFFFFFFFu, rs1, 1);
    rs1 += __shfl_xor_sync(0xFFFFFFFFu, rs1, 2);
    if (tg == 0){ Dsh[w*16 + g] = rs0; Dsh[w*16 + 8 + g] = rs1; }
    __syncthreads();
    if (t < 128) invd[t] = 1.0f / Dsh[t];
    __syncthreads();

    /* vp = v/D as B-frag panel */
    {
        u32* vdst = g_vB + (b*NB + nblk)*PA;
        const float* vb = g_v + (long)b*48*NN + nblk*128;
        for (int j = t; j < PA; j += 256){
            const int reg = j & 1, l5 = (j >> 1) & 31, tile = j >> 6;
            const int kk = tile/6, ct = tile - 6*kk;
            const int c  = ct*8 + (l5 >> 2);
            const int nl = kk*16 + (l5 & 3)*2 + reg*8;
            const float2 vv = *(const float2*)(vb + (long)c*NN + nl);
            vdst[j] = pkh(vv.x*invd[nl], vv.y*invd[nl + 1]);
        }
    }
}

/* ====== Pass 2: recompute S (m rows) -> P in regs -> PV -> out proj ====== */
__global__ __launch_bounds__(256)
void pass2_kernel(const float* __restrict__ wo, const float* __restrict__ bo,
                  float* __restrict__ out)
{
    extern __shared__ char smraw[];
    u32* sK = (u32*)smraw;                  /* [2][3072] u32 */
    u32* sV = sK + 2*PA;                    /* [2][3072] u32 */
    float* wo_s = (float*)(sV + 2*PA);      /* 432 */
    float* bo_s = wo_s + 432;               /* 12 + pad */
    float* attn = (float*)smraw;            /* 48*132 reuse after loop */

    const int t = threadIdx.x, w = t >> 5, lane = t & 31;
    const int g = lane >> 2, tg = lane & 3;
    const int b = blockIdx.y, mt = blockIdx.x;

    for (int i = t; i < 432; i += 256) wo_s[i] = wo[i];
    if (t < 12) bo_s[t] = bo[t];

    /* Q A-frags: warp w owns m-rows w*16..+15 */
    uint4 aq[3];
    {
        const u32* qA = g_qA + (b*NB + mt)*PA;
        #pragma unroll
        for (int ck = 0; ck < 3; ++ck)
            aq[ck] = *(const uint4*)(qA + (w*3 + ck)*128 + lane*4);
    }

    const char* ksrc = (const char*)(g_kB + (long)b*NB*PA);
    const char* vsrc = (const char*)(g_vB + (long)b*NB*PA);
    {
        const u32 dk = smem_u32(sK), dv = smem_u32(sV);
        for (int i = t; i < 768; i += 256){ cpa16(dk + i*16, ksrc + i*16); cpa16(dv + i*16, vsrc + i*16); }
    }
    CP_COMMIT();

    float acc2[6][4];
    #pragma unroll
    for (int ct = 0; ct < 6; ++ct)
        #pragma unroll
        for (int i = 0; i < 4; ++i) acc2[ct][i] = 0.f;

    for (int nc = 0; nc < NB; ++nc){
        const u32* curK = sK + (nc & 1)*PA;
        const u32* curV = sV + (nc & 1)*PA;
        if (nc + 1 < NB){
            const u32 dk = smem_u32(sK + ((nc + 1) & 1)*PA);
            const u32 dv = smem_u32(sV + ((nc + 1) & 1)*PA);
            const char* sk = ksrc + (long)(nc + 1)*PA*4;
            const char* sv = vsrc + (long)(nc + 1)*PA*4;
            for (int i = t; i < 768; i += 256){ cpa16(dk + i*16, sk + i*16); cpa16(dv + i*16, sv + i*16); }
        }
        CP_COMMIT(); CP_WAIT1();
        __syncthreads();

        /* S tiles -> exp -> P A-frags (registers only, output==A identity) */
        u32 pa[8][4];
        #pragma unroll
        for (int j = 0; j < 8; ++j){
            float a0[4] = {0.f,0.f,0.f,0.f}, a1[4] = {0.f,0.f,0.f,0.f};
            #pragma unroll
            for (int ck = 0; ck < 3; ++ck){
                const uint2 b0 = *(const uint2*)(curK + ((2*j    )*3 + ck)*64 + lane*2);
                const uint2 b1 = *(const uint2*)(curK + ((2*j + 1)*3 + ck)*64 + lane*2);
                mma_h(a0, aq[ck], b0);
                mma_h(a1, aq[ck], b1);
            }
            pa[j][0] = pkh(ex2f(fminf(a0[0],15.f)), ex2f(fminf(a0[1],15.f)));
            pa[j][1] = pkh(ex2f(fminf(a0[2],15.f)), ex2f(fminf(a0[3],15.f)));
            pa[j][2] = pkh(ex2f(fminf(a1[0],15.f)), ex2f(fminf(a1[1],15.f)));
            pa[j][3] = pkh(ex2f(fminf(a1[2],15.f)), ex2f(fminf(a1[3],15.f)));
        }

        /* PV: acc2[ct] += P(k16 tile kk) x vp */
        #pragma unroll
        for (int kk = 0; kk < 8; ++kk){
            const uint4 pf = *(const uint4*)pa[kk];
            #pragma unroll
            for (int ct = 0; ct < 6; ++ct){
                const uint2 bv = *(const uint2*)(curV + (kk*6 + ct)*64 + lane*2);
                mma_h(acc2[ct], pf, bv);
            }
        }
        __syncthreads();
    }

    /* stage attn^T [48c x 132m], then output projection */
    __syncthreads();
    #pragma unroll
    for (int ct = 0; ct < 6; ++ct){
        const int m0 = w*16 + g, cb = ct*8 + 2*tg;
        attn[cb*132 + m0]           = acc2[ct][0];
        attn[(cb + 1)*132 + m0]     = acc2[ct][1];
        attn[cb*132 + m0 + 8]       = acc2[ct][2];
        attn[(cb + 1)*132 + m0 + 8] = acc2[ct][3];
    }
    __syncthreads();
    {
        const int og = t >> 7, m = t & 127;
        #pragma unroll
        for (int oo = 0; oo < 6; ++oo){
            const int o = og*6 + oo;
            float s = bo_s[o];
            #pragma unroll
            for (int c = 0; c < 36; ++c) s += wo_s[o*36 + c]*attn[c*132 + m];
            out[((long)(b*12 + o))*NN + mt*128 + m] = s;
        }
    }
}

/* ============================== launch =================================== */
extern "C" void kernel_launch(void* const* d_in, const int* in_sizes, int n_in,
                              void* d_out, int out_size)
{
    const float* x  = (const float*)d_in[0];
    const float* wq = (const float*)d_in[1];
    const float* bq = (const float*)d_in[2];
    const float* wk = (const float*)d_in[3];
    const float* bk = (const float*)d_in[4];
    const float* wv = (const float*)d_in[5];
    const float* bv = (const float*)d_in[6];
    const float* wo = (const float*)d_in[7];
    const float* bo = (const float*)d_in[8];
    float* out = (float*)d_out;

    /* pass2: 4*12288 + 432*4 + 64 = 50944 bytes dynamic smem */
    cudaFuncSetAttribute(pass2_kernel,
                         cudaFuncAttributeMaxDynamicSharedMemorySize, 50944);

    qkv_kernel  <<<dim3(NB, 8), 128>>>(x, wq, bq, wk, bk, wv, bv);
    pass1_kernel<<<dim3(NB, 8), 256>>>();
    pass2_kernel<<<dim3(NB, 8), 256, 50944>>>(wo, bo, out);
}